// round 1
// baseline (speedup 1.0000x reference)
#include <cuda_runtime.h>

// Problem constants
#define NN 16384          // rows (nodes/edges)
#define AA 16384          // rows of bond_n
#define DD 128            // emb dim
#define RS 64             // row splits for column-sum
#define ROWS_PER_SPLIT (AA / RS)   // 256
#define CCHUNK 1024       // columns per colsum block (256 threads * float4)
#define NCB (NN / CCHUNK) // 16

// Scratch (allocation-free rule: __device__ globals)
__device__ float g_Wt[256 * 128];        // transposed Wi_w[2]: [k][d]
__device__ float g_part[RS * NN];        // colsum partials  (4 MB)
__device__ float g_colw[NN];             // bond_n.sum(axis=0)
__device__ float g_mpart[128 * 128];     // m partials
__device__ float g_mv[128];              // m @ Wm[2].T + Wm_b[2]

// ---------------------------------------------------------------------------
// K0: Wt[k*128+d] = Wi_w[2][d][k]   (32768 elems)
// ---------------------------------------------------------------------------
__global__ void k_transpose(const float* __restrict__ Wi_w) {
    int idx = blockIdx.x * blockDim.x + threadIdx.x;   // 0..32767
    int d = idx & 127;
    int k = idx >> 7;
    g_Wt[k * 128 + d] = Wi_w[2 * 128 * 256 + d * 256 + k];
}

// ---------------------------------------------------------------------------
// K1a: partial column sums of bond_n [AA, NN] row-major.
// grid = (NCB, RS), block = 256. Each block: 256 rows x 1024 cols, float4.
// ---------------------------------------------------------------------------
__global__ void k_colsum_part(const float* __restrict__ bond_n) {
    const int cb = blockIdx.x;            // col chunk 0..15
    const int rb = blockIdx.y;            // row split 0..63
    const int c4 = (cb * CCHUNK >> 2) + threadIdx.x;   // float4 index in row
    const float4* __restrict__ src = (const float4*)bond_n;
    const int row0 = rb * ROWS_PER_SPLIT;

    float4 a0 = make_float4(0.f, 0.f, 0.f, 0.f);
    float4 a1 = make_float4(0.f, 0.f, 0.f, 0.f);
    float4 a2 = make_float4(0.f, 0.f, 0.f, 0.f);
    float4 a3 = make_float4(0.f, 0.f, 0.f, 0.f);

    #pragma unroll 1
    for (int r = 0; r < ROWS_PER_SPLIT; r += 4) {
        int base = (row0 + r) * (NN / 4) + c4;
        float4 v0 = src[base];
        float4 v1 = src[base + (NN / 4)];
        float4 v2 = src[base + 2 * (NN / 4)];
        float4 v3 = src[base + 3 * (NN / 4)];
        a0.x += v0.x; a0.y += v0.y; a0.z += v0.z; a0.w += v0.w;
        a1.x += v1.x; a1.y += v1.y; a1.z += v1.z; a1.w += v1.w;
        a2.x += v2.x; a2.y += v2.y; a2.z += v2.z; a2.w += v2.w;
        a3.x += v3.x; a3.y += v3.y; a3.z += v3.z; a3.w += v3.w;
    }
    float4 s;
    s.x = (a0.x + a1.x) + (a2.x + a3.x);
    s.y = (a0.y + a1.y) + (a2.y + a3.y);
    s.z = (a0.z + a1.z) + (a2.z + a3.z);
    s.w = (a0.w + a1.w) + (a2.w + a3.w);
    ((float4*)g_part)[rb * (NN / 4) + c4] = s;
}

// ---------------------------------------------------------------------------
// K1b: reduce RS partials -> col_w. grid = 16, block = 256 (float4 per thread)
// ---------------------------------------------------------------------------
__global__ void k_colsum_reduce() {
    int c4 = blockIdx.x * blockDim.x + threadIdx.x;    // 0..4095
    const float4* __restrict__ p = (const float4*)g_part;
    float4 acc = make_float4(0.f, 0.f, 0.f, 0.f);
    #pragma unroll 4
    for (int rs = 0; rs < RS; rs++) {
        float4 v = p[rs * (NN / 4) + c4];
        acc.x += v.x; acc.y += v.y; acc.z += v.z; acc.w += v.w;
    }
    ((float4*)g_colw)[c4] = acc;
}

// ---------------------------------------------------------------------------
// K2: h_n = relu(cat @ Wi_w[2].T + Wi_b[2])  written to out.
// grid = 512, block = 256 (8 warps). Each warp: 4 rows, lane -> 4 cols.
// ---------------------------------------------------------------------------
__global__ void k_gemm(const int* __restrict__ x, const int* __restrict__ ea,
                       const float* __restrict__ atom_emb,
                       const float* __restrict__ bond_emb,
                       const float* __restrict__ Wi_b,
                       float* __restrict__ out) {
    __shared__ float s_cat[8][4][256];     // 32 KB
    const int warp = threadIdx.x >> 5;
    const int lane = threadIdx.x & 31;
    const int row0 = blockIdx.x * 32 + warp * 4;

    // Build cat rows: [0..127] atom part, [128..255] bond part
    #pragma unroll
    for (int rr = 0; rr < 4; rr++) {
        int n = row0 + rr;
        int a0 = x[2 * n], a1 = x[2 * n + 1];
        int e0 = ea[2 * n], e1 = ea[2 * n + 1];
        #pragma unroll
        for (int j = 0; j < 4; j++) {
            int k = lane + 32 * j;
            s_cat[warp][rr][k]       = atom_emb[a0 * 128 + k] + atom_emb[a1 * 128 + k];
            s_cat[warp][rr][128 + k] = bond_emb[e0 * 128 + k] + bond_emb[e1 * 128 + k];
        }
    }
    __syncwarp();

    float4 acc[4];
    #pragma unroll
    for (int rr = 0; rr < 4; rr++) acc[rr] = make_float4(0.f, 0.f, 0.f, 0.f);

    const float4* __restrict__ Wt4 = (const float4*)g_Wt;   // [k][32 float4]

    #pragma unroll 2
    for (int k4 = 0; k4 < 64; k4++) {
        float4 c0 = ((const float4*)s_cat[warp][0])[k4];
        float4 c1 = ((const float4*)s_cat[warp][1])[k4];
        float4 c2 = ((const float4*)s_cat[warp][2])[k4];
        float4 c3 = ((const float4*)s_cat[warp][3])[k4];
        #pragma unroll
        for (int kk = 0; kk < 4; kk++) {
            int k = k4 * 4 + kk;
            float4 w = Wt4[k * 32 + lane];
            float v0 = (&c0.x)[kk];
            float v1 = (&c1.x)[kk];
            float v2 = (&c2.x)[kk];
            float v3 = (&c3.x)[kk];
            acc[0].x += v0 * w.x; acc[0].y += v0 * w.y; acc[0].z += v0 * w.z; acc[0].w += v0 * w.w;
            acc[1].x += v1 * w.x; acc[1].y += v1 * w.y; acc[1].z += v1 * w.z; acc[1].w += v1 * w.w;
            acc[2].x += v2 * w.x; acc[2].y += v2 * w.y; acc[2].z += v2 * w.z; acc[2].w += v2 * w.w;
            acc[3].x += v3 * w.x; acc[3].y += v3 * w.y; acc[3].z += v3 * w.z; acc[3].w += v3 * w.w;
        }
    }

    float4 b = *(const float4*)&Wi_b[2 * 128 + lane * 4];
    #pragma unroll
    for (int rr = 0; rr < 4; rr++) {
        float4 r;
        r.x = fmaxf(acc[rr].x + b.x, 0.f);
        r.y = fmaxf(acc[rr].y + b.y, 0.f);
        r.z = fmaxf(acc[rr].z + b.z, 0.f);
        r.w = fmaxf(acc[rr].w + b.w, 0.f);
        *(float4*)&out[(row0 + rr) * 128 + lane * 4] = r;
    }
}

// ---------------------------------------------------------------------------
// K3: partial m[d] = sum_{n in block} col_w[n] * h_n[n,d]. grid=128, block=128
// ---------------------------------------------------------------------------
__global__ void k_mpart(const float* __restrict__ hn) {
    const int b = blockIdx.x;
    const int d = threadIdx.x;
    const int n0 = b * 128;
    float acc = 0.f;
    #pragma unroll 4
    for (int i = 0; i < 128; i++) {
        acc += g_colw[n0 + i] * hn[(n0 + i) * 128 + d];
    }
    g_mpart[b * 128 + d] = acc;
}

// ---------------------------------------------------------------------------
// K3b: m = reduce partials;  mv = m @ Wm_w[2].T + Wm_b[2].  1 block, 128 thr.
// ---------------------------------------------------------------------------
__global__ void k_mv(const float* __restrict__ Wm_w, const float* __restrict__ Wm_b) {
    __shared__ float sm[128];
    const int d = threadIdx.x;
    float acc = 0.f;
    #pragma unroll 4
    for (int b = 0; b < 128; b++) acc += g_mpart[b * 128 + d];
    sm[d] = acc;
    __syncthreads();
    float mv = Wm_b[2 * 128 + d];
    const float* __restrict__ wrow = &Wm_w[2 * 128 * 128 + d * 128];
    #pragma unroll 4
    for (int k = 0; k < 128; k++) mv += sm[k] * wrow[k];
    g_mv[d] = mv;
}

// ---------------------------------------------------------------------------
// K4: out = relu(h_n + mv[d])   in-place, float4. grid=2048, block=256
// ---------------------------------------------------------------------------
__global__ void k_addrelu(float* __restrict__ out) {
    int g = blockIdx.x * blockDim.x + threadIdx.x;     // 0..524287
    int d0 = (g * 4) & 127;
    float4 v = ((const float4*)out)[g];
    float4 m = *(const float4*)&g_mv[d0];
    v.x = fmaxf(v.x + m.x, 0.f);
    v.y = fmaxf(v.y + m.y, 0.f);
    v.z = fmaxf(v.z + m.z, 0.f);
    v.w = fmaxf(v.w + m.w, 0.f);
    ((float4*)out)[g] = v;
}

// ---------------------------------------------------------------------------
extern "C" void kernel_launch(void* const* d_in, const int* in_sizes, int n_in,
                              void* d_out, int out_size) {
    const int*   x        = (const int*)d_in[0];
    const int*   ea       = (const int*)d_in[1];
    const float* bond_n   = (const float*)d_in[2];
    const float* atom_emb = (const float*)d_in[3];
    const float* bond_emb = (const float*)d_in[4];
    const float* Wi_w     = (const float*)d_in[5];
    const float* Wi_b     = (const float*)d_in[6];
    const float* Wm_w     = (const float*)d_in[7];
    const float* Wm_b     = (const float*)d_in[8];
    float* out = (float*)d_out;

    k_transpose<<<128, 256>>>(Wi_w);

    dim3 g1(NCB, RS);
    k_colsum_part<<<g1, 256>>>(bond_n);
    k_colsum_reduce<<<16, 256>>>();

    k_gemm<<<512, 256>>>(x, ea, atom_emb, bond_emb, Wi_b, out);

    k_mpart<<<128, 128>>>(out);
    k_mv<<<1, 128>>>(Wm_w, Wm_b);
    k_addrelu<<<2048, 256>>>(out);
}

// round 2
// speedup vs baseline: 1.2224x; 1.2224x over previous
#include <cuda_runtime.h>

// Problem constants
#define NN 16384          // cols of bond_n / rows of h
#define AA 16384          // rows of bond_n
#define RS 64             // row splits for column-sum
#define ROWS_PER_SPLIT (AA / RS)   // 256
#define CCHUNK 1024       // columns per colsum block (256 threads * float4)
#define NCB (NN / CCHUNK) // 16
#define G_GEMM 512
#define G_COL  (NCB * RS) // 1024
#define G_TOT  (G_GEMM + G_COL)  // 1536

// Scratch (allocation-free rule: __device__ globals)
__device__ float g_Wt[256 * 128];        // transposed Wi_w[2]: [k][d]
__device__ float g_part[RS * NN];        // colsum partials  (4 MB)
__device__ float g_mpart[128 * 128];     // m partials
__device__ float g_mv[128];              // m @ Wm[2].T + Wm_b[2]

// ---------------------------------------------------------------------------
// K0: Wt[k*128+d] = Wi_w[2][d][k]   (32768 elems)
// ---------------------------------------------------------------------------
__global__ void k_transpose(const float* __restrict__ Wi_w) {
    int idx = blockIdx.x * blockDim.x + threadIdx.x;   // 0..32767
    int d = idx & 127;
    int k = idx >> 7;
    g_Wt[k * 128 + d] = Wi_w[2 * 128 * 256 + d * 256 + k];
}

// ---------------------------------------------------------------------------
// K1 (FUSED): block role by blockIdx.
//   b % 3 == 0  -> gemm block   (512 blocks):  h_n = relu(cat @ Wi^T + b)
//   otherwise   -> colsum block (1024 blocks): partial col sums of bond_n
// The gemm's FMA work hides inside the colsum's DRAM shadow.
// ---------------------------------------------------------------------------
__global__ void __launch_bounds__(256) k_fused(
        const int* __restrict__ x, const int* __restrict__ ea,
        const float* __restrict__ atom_emb,
        const float* __restrict__ bond_emb,
        const float* __restrict__ Wi_b,
        const float* __restrict__ bond_n,
        float* __restrict__ out) {
    __shared__ float s_cat[8][4][256];     // 32 KB (gemm path only)
    const int b = blockIdx.x;

    if (b % 3 == 0) {
        // ---------------- GEMM role ----------------
        const int gb   = b / 3;                  // 0..511
        const int warp = threadIdx.x >> 5;
        const int lane = threadIdx.x & 31;
        const int row0 = gb * 32 + warp * 4;

        #pragma unroll
        for (int rr = 0; rr < 4; rr++) {
            int n = row0 + rr;
            int a0 = x[2 * n], a1 = x[2 * n + 1];
            int e0 = ea[2 * n], e1 = ea[2 * n + 1];
            #pragma unroll
            for (int j = 0; j < 4; j++) {
                int k = lane + 32 * j;
                s_cat[warp][rr][k]       = atom_emb[a0 * 128 + k] + atom_emb[a1 * 128 + k];
                s_cat[warp][rr][128 + k] = bond_emb[e0 * 128 + k] + bond_emb[e1 * 128 + k];
            }
        }
        __syncwarp();

        float4 acc[4];
        #pragma unroll
        for (int rr = 0; rr < 4; rr++) acc[rr] = make_float4(0.f, 0.f, 0.f, 0.f);

        const float4* __restrict__ Wt4 = (const float4*)g_Wt;   // [k][32 float4]

        #pragma unroll 2
        for (int k4 = 0; k4 < 64; k4++) {
            float4 c0 = ((const float4*)s_cat[warp][0])[k4];
            float4 c1 = ((const float4*)s_cat[warp][1])[k4];
            float4 c2 = ((const float4*)s_cat[warp][2])[k4];
            float4 c3 = ((const float4*)s_cat[warp][3])[k4];
            #pragma unroll
            for (int kk = 0; kk < 4; kk++) {
                int k = k4 * 4 + kk;
                float4 w = Wt4[k * 32 + lane];
                float v0 = (&c0.x)[kk];
                float v1 = (&c1.x)[kk];
                float v2 = (&c2.x)[kk];
                float v3 = (&c3.x)[kk];
                acc[0].x += v0 * w.x; acc[0].y += v0 * w.y; acc[0].z += v0 * w.z; acc[0].w += v0 * w.w;
                acc[1].x += v1 * w.x; acc[1].y += v1 * w.y; acc[1].z += v1 * w.z; acc[1].w += v1 * w.w;
                acc[2].x += v2 * w.x; acc[2].y += v2 * w.y; acc[2].z += v2 * w.z; acc[2].w += v2 * w.w;
                acc[3].x += v3 * w.x; acc[3].y += v3 * w.y; acc[3].z += v3 * w.z; acc[3].w += v3 * w.w;
            }
        }

        float4 bias = *(const float4*)&Wi_b[2 * 128 + lane * 4];
        #pragma unroll
        for (int rr = 0; rr < 4; rr++) {
            float4 r;
            r.x = fmaxf(acc[rr].x + bias.x, 0.f);
            r.y = fmaxf(acc[rr].y + bias.y, 0.f);
            r.z = fmaxf(acc[rr].z + bias.z, 0.f);
            r.w = fmaxf(acc[rr].w + bias.w, 0.f);
            *(float4*)&out[(row0 + rr) * 128 + lane * 4] = r;
        }
    } else {
        // ---------------- COLSUM role ----------------
        const int ci = b - b / 3 - 1;               // 0..1023
        const int rb = ci >> 4;                     // row split 0..63
        const int cb = ci & 15;                     // col chunk 0..15
        const int c4 = (cb * CCHUNK >> 2) + threadIdx.x;   // float4 index in row
        const float4* __restrict__ src = (const float4*)bond_n;
        const int row0 = rb * ROWS_PER_SPLIT;

        float4 a0 = make_float4(0.f, 0.f, 0.f, 0.f);
        float4 a1 = make_float4(0.f, 0.f, 0.f, 0.f);
        float4 a2 = make_float4(0.f, 0.f, 0.f, 0.f);
        float4 a3 = make_float4(0.f, 0.f, 0.f, 0.f);

        #pragma unroll 1
        for (int r = 0; r < ROWS_PER_SPLIT; r += 8) {
            long base = (long)(row0 + r) * (NN / 4) + c4;
            float4 v0 = src[base];
            float4 v1 = src[base + 1 * (NN / 4)];
            float4 v2 = src[base + 2 * (NN / 4)];
            float4 v3 = src[base + 3 * (NN / 4)];
            float4 v4 = src[base + 4 * (NN / 4)];
            float4 v5 = src[base + 5 * (NN / 4)];
            float4 v6 = src[base + 6 * (NN / 4)];
            float4 v7 = src[base + 7 * (NN / 4)];
            a0.x += v0.x; a0.y += v0.y; a0.z += v0.z; a0.w += v0.w;
            a1.x += v1.x; a1.y += v1.y; a1.z += v1.z; a1.w += v1.w;
            a2.x += v2.x; a2.y += v2.y; a2.z += v2.z; a2.w += v2.w;
            a3.x += v3.x; a3.y += v3.y; a3.z += v3.z; a3.w += v3.w;
            a0.x += v4.x; a0.y += v4.y; a0.z += v4.z; a0.w += v4.w;
            a1.x += v5.x; a1.y += v5.y; a1.z += v5.z; a1.w += v5.w;
            a2.x += v6.x; a2.y += v6.y; a2.z += v6.z; a2.w += v6.w;
            a3.x += v7.x; a3.y += v7.y; a3.z += v7.z; a3.w += v7.w;
        }
        float4 s;
        s.x = (a0.x + a1.x) + (a2.x + a3.x);
        s.y = (a0.y + a1.y) + (a2.y + a3.y);
        s.z = (a0.z + a1.z) + (a2.z + a3.z);
        s.w = (a0.w + a1.w) + (a2.w + a3.w);
        ((float4*)g_part)[rb * (NN / 4) + c4] = s;
    }
}

// ---------------------------------------------------------------------------
// K2 (FUSED reduce + mpart): grid=128, block=128.
// Block bk: colw[n] for n in [bk*128, bk*128+128) reduced in smem, then
// partial m[d] = sum_n colw[n] * h_n[n,d].
// ---------------------------------------------------------------------------
__global__ void k_mpart(const float* __restrict__ hn) {
    __shared__ float colw_s[128];
    const int bk = blockIdx.x;
    const int d  = threadIdx.x;
    const int n0 = bk * 128;

    float cw = 0.f;
    #pragma unroll 8
    for (int rs = 0; rs < RS; rs++)
        cw += g_part[rs * NN + n0 + d];
    colw_s[d] = cw;
    __syncthreads();

    float acc = 0.f;
    #pragma unroll 4
    for (int i = 0; i < 128; i++)
        acc += colw_s[i] * hn[(n0 + i) * 128 + d];
    g_mpart[bk * 128 + d] = acc;
}

// ---------------------------------------------------------------------------
// K3: m = reduce partials; mv = m @ Wm_w[2].T + Wm_b[2].  1 block, 128 thr.
// ---------------------------------------------------------------------------
__global__ void k_mv(const float* __restrict__ Wm_w, const float* __restrict__ Wm_b) {
    __shared__ float sm[128];
    const int d = threadIdx.x;
    float acc = 0.f;
    #pragma unroll 4
    for (int b = 0; b < 128; b++) acc += g_mpart[b * 128 + d];
    sm[d] = acc;
    __syncthreads();
    float mv = Wm_b[2 * 128 + d];
    const float* __restrict__ wrow = &Wm_w[2 * 128 * 128 + d * 128];
    #pragma unroll 4
    for (int k = 0; k < 128; k++) mv += sm[k] * wrow[k];
    g_mv[d] = mv;
}

// ---------------------------------------------------------------------------
// K4: out = relu(h_n + mv[d])   in-place, float4. grid=2048, block=256
// ---------------------------------------------------------------------------
__global__ void k_addrelu(float* __restrict__ out) {
    int g = blockIdx.x * blockDim.x + threadIdx.x;     // 0..524287
    int d0 = (g * 4) & 127;
    float4 v = ((const float4*)out)[g];
    float4 m = *(const float4*)&g_mv[d0];
    v.x = fmaxf(v.x + m.x, 0.f);
    v.y = fmaxf(v.y + m.y, 0.f);
    v.z = fmaxf(v.z + m.z, 0.f);
    v.w = fmaxf(v.w + m.w, 0.f);
    ((float4*)out)[g] = v;
}

// ---------------------------------------------------------------------------
extern "C" void kernel_launch(void* const* d_in, const int* in_sizes, int n_in,
                              void* d_out, int out_size) {
    const int*   x        = (const int*)d_in[0];
    const int*   ea       = (const int*)d_in[1];
    const float* bond_n   = (const float*)d_in[2];
    const float* atom_emb = (const float*)d_in[3];
    const float* bond_emb = (const float*)d_in[4];
    const float* Wi_w     = (const float*)d_in[5];
    const float* Wi_b     = (const float*)d_in[6];
    const float* Wm_w     = (const float*)d_in[7];
    const float* Wm_b     = (const float*)d_in[8];
    float* out = (float*)d_out;

    k_transpose<<<128, 256>>>(Wi_w);
    k_fused<<<G_TOT, 256>>>(x, ea, atom_emb, bond_emb, Wi_b, bond_n, out);
    k_mpart<<<128, 128>>>(out);
    k_mv<<<1, 128>>>(Wm_w, Wm_b);
    k_addrelu<<<2048, 256>>>(out);
}

// round 3
// speedup vs baseline: 1.5012x; 1.2280x over previous
#include <cuda_runtime.h>

// Problem constants
#define NN 16384          // cols of bond_n / rows of h
#define AA 16384          // rows of bond_n
#define RS 64             // row splits for column-sum
#define ROWS_PER_SPLIT (AA / RS)   // 256
#define CCHUNK 1024       // columns per colsum block (256 threads * float4)
#define NCB (NN / CCHUNK) // 16
#define G_GEMM 512
#define G_COL  (NCB * RS) // 1024
#define G_TOT  (G_GEMM + G_COL)  // 1536

// Scratch (allocation-free rule: __device__ globals)
__device__ float g_Wt[256 * 128];        // transposed Wi_w[2]: [k][d]
__device__ float g_part[RS * NN];        // colsum partials  (4 MB)
__device__ float g_mpart[128 * 128];     // m partials
__device__ float g_mv[128];              // m @ Wm[2].T + Wm_b[2]

// ---------------------------------------------------------------------------
// K0: Wt[k*128+d] = Wi_w[2][d][k]   (32768 elems)
// ---------------------------------------------------------------------------
__global__ void k_transpose(const float* __restrict__ Wi_w) {
    int idx = blockIdx.x * blockDim.x + threadIdx.x;   // 0..32767
    int d = idx & 127;
    int k = idx >> 7;
    g_Wt[k * 128 + d] = Wi_w[2 * 128 * 256 + d * 256 + k];
}

// ---------------------------------------------------------------------------
// K1 (FUSED): block role by blockIdx.
//   b % 3 == 0  -> gemm block   (512 blocks):  h_n = relu(cat @ Wi^T + b)
//   otherwise   -> colsum block (1024 blocks): partial col sums of bond_n
// ---------------------------------------------------------------------------
__global__ void __launch_bounds__(256) k_fused(
        const int* __restrict__ x, const int* __restrict__ ea,
        const float* __restrict__ atom_emb,
        const float* __restrict__ bond_emb,
        const float* __restrict__ Wi_b,
        const float* __restrict__ bond_n,
        float* __restrict__ out) {
    __shared__ float s_cat[8][4][256];     // 32 KB (gemm path only)
    const int b = blockIdx.x;

    if (b % 3 == 0) {
        // ---------------- GEMM role ----------------
        const int gb   = b / 3;                  // 0..511
        const int warp = threadIdx.x >> 5;
        const int lane = threadIdx.x & 31;
        const int row0 = gb * 32 + warp * 4;

        #pragma unroll
        for (int rr = 0; rr < 4; rr++) {
            int n = row0 + rr;
            int a0 = x[2 * n], a1 = x[2 * n + 1];
            int e0 = ea[2 * n], e1 = ea[2 * n + 1];
            #pragma unroll
            for (int j = 0; j < 4; j++) {
                int k = lane + 32 * j;
                s_cat[warp][rr][k]       = atom_emb[a0 * 128 + k] + atom_emb[a1 * 128 + k];
                s_cat[warp][rr][128 + k] = bond_emb[e0 * 128 + k] + bond_emb[e1 * 128 + k];
            }
        }
        __syncwarp();

        float4 acc[4];
        #pragma unroll
        for (int rr = 0; rr < 4; rr++) acc[rr] = make_float4(0.f, 0.f, 0.f, 0.f);

        const float4* __restrict__ Wt4 = (const float4*)g_Wt;   // [k][32 float4]

        #pragma unroll 2
        for (int k4 = 0; k4 < 64; k4++) {
            float4 c0 = ((const float4*)s_cat[warp][0])[k4];
            float4 c1 = ((const float4*)s_cat[warp][1])[k4];
            float4 c2 = ((const float4*)s_cat[warp][2])[k4];
            float4 c3 = ((const float4*)s_cat[warp][3])[k4];
            #pragma unroll
            for (int kk = 0; kk < 4; kk++) {
                int k = k4 * 4 + kk;
                float4 w = Wt4[k * 32 + lane];
                float v0 = (&c0.x)[kk];
                float v1 = (&c1.x)[kk];
                float v2 = (&c2.x)[kk];
                float v3 = (&c3.x)[kk];
                acc[0].x += v0 * w.x; acc[0].y += v0 * w.y; acc[0].z += v0 * w.z; acc[0].w += v0 * w.w;
                acc[1].x += v1 * w.x; acc[1].y += v1 * w.y; acc[1].z += v1 * w.z; acc[1].w += v1 * w.w;
                acc[2].x += v2 * w.x; acc[2].y += v2 * w.y; acc[2].z += v2 * w.z; acc[2].w += v2 * w.w;
                acc[3].x += v3 * w.x; acc[3].y += v3 * w.y; acc[3].z += v3 * w.z; acc[3].w += v3 * w.w;
            }
        }

        float4 bias = *(const float4*)&Wi_b[2 * 128 + lane * 4];
        #pragma unroll
        for (int rr = 0; rr < 4; rr++) {
            float4 r;
            r.x = fmaxf(acc[rr].x + bias.x, 0.f);
            r.y = fmaxf(acc[rr].y + bias.y, 0.f);
            r.z = fmaxf(acc[rr].z + bias.z, 0.f);
            r.w = fmaxf(acc[rr].w + bias.w, 0.f);
            *(float4*)&out[(row0 + rr) * 128 + lane * 4] = r;
        }
    } else {
        // ---------------- COLSUM role ----------------
        const int ci = b - b / 3 - 1;               // 0..1023
        const int rb = ci >> 4;                     // row split 0..63
        const int cb = ci & 15;                     // col chunk 0..15
        const int c4 = (cb * CCHUNK >> 2) + threadIdx.x;   // float4 index in row
        const float4* __restrict__ src = (const float4*)bond_n;
        const int row0 = rb * ROWS_PER_SPLIT;

        float4 a0 = make_float4(0.f, 0.f, 0.f, 0.f);
        float4 a1 = make_float4(0.f, 0.f, 0.f, 0.f);
        float4 a2 = make_float4(0.f, 0.f, 0.f, 0.f);
        float4 a3 = make_float4(0.f, 0.f, 0.f, 0.f);

        #pragma unroll 1
        for (int r = 0; r < ROWS_PER_SPLIT; r += 8) {
            long base = (long)(row0 + r) * (NN / 4) + c4;
            float4 v0 = src[base];
            float4 v1 = src[base + 1 * (NN / 4)];
            float4 v2 = src[base + 2 * (NN / 4)];
            float4 v3 = src[base + 3 * (NN / 4)];
            float4 v4 = src[base + 4 * (NN / 4)];
            float4 v5 = src[base + 5 * (NN / 4)];
            float4 v6 = src[base + 6 * (NN / 4)];
            float4 v7 = src[base + 7 * (NN / 4)];
            a0.x += v0.x; a0.y += v0.y; a0.z += v0.z; a0.w += v0.w;
            a1.x += v1.x; a1.y += v1.y; a1.z += v1.z; a1.w += v1.w;
            a2.x += v2.x; a2.y += v2.y; a2.z += v2.z; a2.w += v2.w;
            a3.x += v3.x; a3.y += v3.y; a3.z += v3.z; a3.w += v3.w;
            a0.x += v4.x; a0.y += v4.y; a0.z += v4.z; a0.w += v4.w;
            a1.x += v5.x; a1.y += v5.y; a1.z += v5.z; a1.w += v5.w;
            a2.x += v6.x; a2.y += v6.y; a2.z += v6.z; a2.w += v6.w;
            a3.x += v7.x; a3.y += v7.y; a3.z += v7.z; a3.w += v7.w;
        }
        float4 s;
        s.x = (a0.x + a1.x) + (a2.x + a3.x);
        s.y = (a0.y + a1.y) + (a2.y + a3.y);
        s.z = (a0.z + a1.z) + (a2.z + a3.z);
        s.w = (a0.w + a1.w) + (a2.w + a3.w);
        ((float4*)g_part)[rb * (NN / 4) + c4] = s;
    }
}

// ---------------------------------------------------------------------------
// K2 (reduce + mpart): grid=128, block=128.
// Block bk: colw[n] for n in [bk*128, bk*128+128) reduced in smem, then
// partial m[d] = sum_n colw[n] * h_n[n,d].
// ---------------------------------------------------------------------------
__global__ void k_mpart(const float* __restrict__ hn) {
    __shared__ float colw_s[128];
    const int bk = blockIdx.x;
    const int d  = threadIdx.x;
    const int n0 = bk * 128;

    float cw = 0.f;
    #pragma unroll 8
    for (int rs = 0; rs < RS; rs++)
        cw += g_part[rs * NN + n0 + d];
    colw_s[d] = cw;
    __syncthreads();

    float acc = 0.f;
    #pragma unroll 8
    for (int i = 0; i < 128; i++)
        acc += colw_s[i] * __ldg(&hn[(n0 + i) * 128 + d]);
    g_mpart[bk * 128 + d] = acc;
}

// ---------------------------------------------------------------------------
// K3: mv[d] = Wm_b[2][d] + sum_k m[k] * Wm_w[2][d][k],
//     m[k] = sum_b g_mpart[b][k].
// grid = 128 (one block per d), block = 128 (one thread per k).
// Redundant m-reduction per block is L2-hot (64 KB) — cheap; buys 128-SM
// parallelism vs the old 1-block serial version.
// ---------------------------------------------------------------------------
__global__ void k_mv(const float* __restrict__ Wm_w, const float* __restrict__ Wm_b) {
    const int d = blockIdx.x;
    const int k = threadIdx.x;

    float m = 0.f;
    #pragma unroll 8
    for (int b = 0; b < 128; b++)
        m += g_mpart[b * 128 + k];

    float p = m * __ldg(&Wm_w[2 * 128 * 128 + d * 128 + k]);

    #pragma unroll
    for (int o = 16; o > 0; o >>= 1)
        p += __shfl_xor_sync(0xffffffffu, p, o);

    __shared__ float ws[4];
    if ((k & 31) == 0) ws[k >> 5] = p;
    __syncthreads();
    if (k == 0)
        g_mv[d] = Wm_b[2 * 128 + d] + ((ws[0] + ws[1]) + (ws[2] + ws[3]));
}

// ---------------------------------------------------------------------------
// K4: out = relu(h_n + mv[d])   in-place, float4. grid=2048, block=256
// ---------------------------------------------------------------------------
__global__ void k_addrelu(float* __restrict__ out) {
    int g = blockIdx.x * blockDim.x + threadIdx.x;     // 0..524287
    int d0 = (g * 4) & 127;
    float4 v = ((const float4*)out)[g];
    float4 m = *(const float4*)&g_mv[d0];
    v.x = fmaxf(v.x + m.x, 0.f);
    v.y = fmaxf(v.y + m.y, 0.f);
    v.z = fmaxf(v.z + m.z, 0.f);
    v.w = fmaxf(v.w + m.w, 0.f);
    ((float4*)out)[g] = v;
}

// ---------------------------------------------------------------------------
extern "C" void kernel_launch(void* const* d_in, const int* in_sizes, int n_in,
                              void* d_out, int out_size) {
    const int*   x        = (const int*)d_in[0];
    const int*   ea       = (const int*)d_in[1];
    const float* bond_n   = (const float*)d_in[2];
    const float* atom_emb = (const float*)d_in[3];
    const float* bond_emb = (const float*)d_in[4];
    const float* Wi_w     = (const float*)d_in[5];
    const float* Wi_b     = (const float*)d_in[6];
    const float* Wm_w     = (const float*)d_in[7];
    const float* Wm_b     = (const float*)d_in[8];
    float* out = (float*)d_out;

    k_transpose<<<128, 256>>>(Wi_w);
    k_fused<<<G_TOT, 256>>>(x, ea, atom_emb, bond_emb, Wi_b, bond_n, out);
    k_mpart<<<128, 128>>>(out);
    k_mv<<<1 * 128, 128>>>(Wm_w, Wm_b);
    k_addrelu<<<2048, 256>>>(out);
}

// round 4
// speedup vs baseline: 1.5075x; 1.0042x over previous
#include <cuda_runtime.h>

// Problem constants
#define NN 16384          // cols of bond_n / rows of h
#define AA 16384          // rows of bond_n
#define RS 64             // row splits for column-sum
#define ROWS_PER_SPLIT (AA / RS)   // 256
#define CCHUNK 1024       // columns per colsum block (256 threads * float4)
#define NCB (NN / CCHUNK) // 16
#define G_GEMM 512
#define G_COL  (NCB * RS) // 1024
#define G_TOT  (G_GEMM + G_COL)  // 1536
#define TB     128        // tail blocks (<=148 -> all co-resident)

// Scratch (allocation-free rule: __device__ globals)
__device__ float g_Wt[256 * 128];        // transposed Wi_w[2]: [k][d]
__device__ float g_part[RS * NN];        // colsum partials  (4 MB)
__device__ float g_mpart[TB * 128];      // m partials
__device__ float g_mv[128];              // m @ Wm[2].T + Wm_b[2]
__device__ int   g_cnt;                  // tail arrival counter
__device__ int   g_flag;                 // mv-published flag

// ---------------------------------------------------------------------------
// K0: Wt[k*128+d] = Wi_w[2][d][k]; also resets tail sync state each replay.
// ---------------------------------------------------------------------------
__global__ void k_transpose(const float* __restrict__ Wi_w) {
    int idx = blockIdx.x * blockDim.x + threadIdx.x;   // 0..32767
    if (idx == 0) { g_cnt = 0; g_flag = 0; }
    int d = idx & 127;
    int k = idx >> 7;
    g_Wt[k * 128 + d] = Wi_w[2 * 128 * 256 + d * 256 + k];
}

// ---------------------------------------------------------------------------
// K1 (FUSED): block role by blockIdx.
//   b % 3 == 0  -> gemm block   (512 blocks):  h_n = relu(cat @ Wi^T + b)
//   otherwise   -> colsum block (1024 blocks): partial col sums of bond_n
// ---------------------------------------------------------------------------
__global__ void __launch_bounds__(256) k_fused(
        const int* __restrict__ x, const int* __restrict__ ea,
        const float* __restrict__ atom_emb,
        const float* __restrict__ bond_emb,
        const float* __restrict__ Wi_b,
        const float* __restrict__ bond_n,
        float* __restrict__ out) {
    __shared__ float s_cat[8][4][256];     // 32 KB (gemm path only)
    const int b = blockIdx.x;

    if (b % 3 == 0) {
        // ---------------- GEMM role ----------------
        const int gb   = b / 3;                  // 0..511
        const int warp = threadIdx.x >> 5;
        const int lane = threadIdx.x & 31;
        const int row0 = gb * 32 + warp * 4;

        #pragma unroll
        for (int rr = 0; rr < 4; rr++) {
            int n = row0 + rr;
            int a0 = x[2 * n], a1 = x[2 * n + 1];
            int e0 = ea[2 * n], e1 = ea[2 * n + 1];
            #pragma unroll
            for (int j = 0; j < 4; j++) {
                int k = lane + 32 * j;
                s_cat[warp][rr][k]       = atom_emb[a0 * 128 + k] + atom_emb[a1 * 128 + k];
                s_cat[warp][rr][128 + k] = bond_emb[e0 * 128 + k] + bond_emb[e1 * 128 + k];
            }
        }
        __syncwarp();

        float4 acc[4];
        #pragma unroll
        for (int rr = 0; rr < 4; rr++) acc[rr] = make_float4(0.f, 0.f, 0.f, 0.f);

        const float4* __restrict__ Wt4 = (const float4*)g_Wt;   // [k][32 float4]

        #pragma unroll 2
        for (int k4 = 0; k4 < 64; k4++) {
            float4 c0 = ((const float4*)s_cat[warp][0])[k4];
            float4 c1 = ((const float4*)s_cat[warp][1])[k4];
            float4 c2 = ((const float4*)s_cat[warp][2])[k4];
            float4 c3 = ((const float4*)s_cat[warp][3])[k4];
            #pragma unroll
            for (int kk = 0; kk < 4; kk++) {
                int k = k4 * 4 + kk;
                float4 w = Wt4[k * 32 + lane];
                float v0 = (&c0.x)[kk];
                float v1 = (&c1.x)[kk];
                float v2 = (&c2.x)[kk];
                float v3 = (&c3.x)[kk];
                acc[0].x += v0 * w.x; acc[0].y += v0 * w.y; acc[0].z += v0 * w.z; acc[0].w += v0 * w.w;
                acc[1].x += v1 * w.x; acc[1].y += v1 * w.y; acc[1].z += v1 * w.z; acc[1].w += v1 * w.w;
                acc[2].x += v2 * w.x; acc[2].y += v2 * w.y; acc[2].z += v2 * w.z; acc[2].w += v2 * w.w;
                acc[3].x += v3 * w.x; acc[3].y += v3 * w.y; acc[3].z += v3 * w.z; acc[3].w += v3 * w.w;
            }
        }

        float4 bias = *(const float4*)&Wi_b[2 * 128 + lane * 4];
        #pragma unroll
        for (int rr = 0; rr < 4; rr++) {
            float4 r;
            r.x = fmaxf(acc[rr].x + bias.x, 0.f);
            r.y = fmaxf(acc[rr].y + bias.y, 0.f);
            r.z = fmaxf(acc[rr].z + bias.z, 0.f);
            r.w = fmaxf(acc[rr].w + bias.w, 0.f);
            *(float4*)&out[(row0 + rr) * 128 + lane * 4] = r;
        }
    } else {
        // ---------------- COLSUM role ----------------
        const int ci = b - b / 3 - 1;               // 0..1023
        const int rb = ci >> 4;                     // row split 0..63
        const int cb = ci & 15;                     // col chunk 0..15
        const int c4 = (cb * CCHUNK >> 2) + threadIdx.x;   // float4 index in row
        const float4* __restrict__ src = (const float4*)bond_n;
        const int row0 = rb * ROWS_PER_SPLIT;

        float4 a0 = make_float4(0.f, 0.f, 0.f, 0.f);
        float4 a1 = make_float4(0.f, 0.f, 0.f, 0.f);
        float4 a2 = make_float4(0.f, 0.f, 0.f, 0.f);
        float4 a3 = make_float4(0.f, 0.f, 0.f, 0.f);

        #pragma unroll 1
        for (int r = 0; r < ROWS_PER_SPLIT; r += 8) {
            long base = (long)(row0 + r) * (NN / 4) + c4;
            float4 v0 = src[base];
            float4 v1 = src[base + 1 * (NN / 4)];
            float4 v2 = src[base + 2 * (NN / 4)];
            float4 v3 = src[base + 3 * (NN / 4)];
            float4 v4 = src[base + 4 * (NN / 4)];
            float4 v5 = src[base + 5 * (NN / 4)];
            float4 v6 = src[base + 6 * (NN / 4)];
            float4 v7 = src[base + 7 * (NN / 4)];
            a0.x += v0.x; a0.y += v0.y; a0.z += v0.z; a0.w += v0.w;
            a1.x += v1.x; a1.y += v1.y; a1.z += v1.z; a1.w += v1.w;
            a2.x += v2.x; a2.y += v2.y; a2.z += v2.z; a2.w += v2.w;
            a3.x += v3.x; a3.y += v3.y; a3.z += v3.z; a3.w += v3.w;
            a0.x += v4.x; a0.y += v4.y; a0.z += v4.z; a0.w += v4.w;
            a1.x += v5.x; a1.y += v5.y; a1.z += v5.z; a1.w += v5.w;
            a2.x += v6.x; a2.y += v6.y; a2.z += v6.z; a2.w += v6.w;
            a3.x += v7.x; a3.y += v7.y; a3.z += v7.z; a3.w += v7.w;
        }
        float4 s;
        s.x = (a0.x + a1.x) + (a2.x + a3.x);
        s.y = (a0.y + a1.y) + (a2.y + a3.y);
        s.z = (a0.z + a1.z) + (a2.z + a3.z);
        s.w = (a0.w + a1.w) + (a2.w + a3.w);
        ((float4*)g_part)[rb * (NN / 4) + c4] = s;
    }
}

// ---------------------------------------------------------------------------
// K2 (FUSED TAIL): grid=128 blocks x 256 threads, all co-resident.
// Phase A: block bk -> colw for n in [bk*128, +128), then mpart[bk][d].
// Phase B: last-arriving block reduces m, computes mv, publishes flag.
// Phase C: all blocks spin on flag, then relu(h + mv) on their 128 rows.
// ---------------------------------------------------------------------------
__global__ void __launch_bounds__(256) k_tail(
        const float* __restrict__ Wm_w, const float* __restrict__ Wm_b,
        float* __restrict__ out) {
    __shared__ float colw2[2][128];
    __shared__ float colw_s[128];
    __shared__ float part2[2][128];
    __shared__ float sm_m[128];
    __shared__ float mv_s[128];
    __shared__ int   is_last;

    const int bk  = blockIdx.x;
    const int tid = threadIdx.x;
    const int d   = tid & 127;
    const int h   = tid >> 7;          // 0 or 1
    const int n0  = bk * 128;

    // --- Phase A1: colw (split RS=64 over two halves) ---
    float cw = 0.f;
    #pragma unroll 8
    for (int rs = h * 32; rs < h * 32 + 32; rs++)
        cw += g_part[rs * NN + n0 + d];
    colw2[h][d] = cw;
    __syncthreads();
    if (h == 0) colw_s[d] = colw2[0][d] + colw2[1][d];
    __syncthreads();

    // --- Phase A2: mpart[d] = sum_i colw[i] * h[n0+i][d] (split i) ---
    float acc = 0.f;
    #pragma unroll 8
    for (int i = h * 64; i < h * 64 + 64; i++)
        acc += colw_s[i] * __ldg(&out[(n0 + i) * 128 + d]);
    part2[h][d] = acc;
    __syncthreads();
    if (h == 0) g_mpart[bk * 128 + d] = part2[0][d] + part2[1][d];

    // --- Phase B: elect last block ---
    __threadfence();
    if (tid == 0) {
        int old = atomicAdd(&g_cnt, 1);
        is_last = (old == TB - 1);
    }
    __syncthreads();

    if (is_last) {
        // m[k] = sum_b g_mpart[b][k]   (k = d, split b over halves)
        float m = 0.f;
        #pragma unroll 8
        for (int b = h * 64; b < h * 64 + 64; b++)
            m += g_mpart[b * 128 + d];
        part2[h][d] = m;
        __syncthreads();
        if (h == 0) sm_m[d] = part2[0][d] + part2[1][d];
        __syncthreads();

        // mv[d] = bias + sum_k m[k] * Wm_w[2][d][k]   (split k)
        float p = 0.f;
        const float* __restrict__ wrow = &Wm_w[2 * 128 * 128 + d * 128];
        #pragma unroll 8
        for (int k = h * 64; k < h * 64 + 64; k++)
            p += sm_m[k] * __ldg(&wrow[k]);
        part2[h][d] = p;
        __syncthreads();
        if (h == 0)
            g_mv[d] = Wm_b[2 * 128 + d] + part2[0][d] + part2[1][d];
        __threadfence();
        __syncthreads();
        if (tid == 0) atomicExch(&g_flag, 1);
    }

    // --- Phase C: wait for mv, then relu(h + mv) on own rows ---
    if (tid == 0) {
        while (atomicAdd(&g_flag, 0) == 0) { }
    }
    __syncthreads();
    mv_s[d] = g_mv[d];
    __syncthreads();

    float4* __restrict__ o4 = (float4*)&out[(long)n0 * 128];
    #pragma unroll 4
    for (int i = tid; i < 128 * 32; i += 256) {       // 4096 float4 per block
        float4 v = o4[i];
        int d0 = (i * 4) & 127;
        float4 m4 = *(const float4*)&mv_s[d0];
        v.x = fmaxf(v.x + m4.x, 0.f);
        v.y = fmaxf(v.y + m4.y, 0.f);
        v.z = fmaxf(v.z + m4.z, 0.f);
        v.w = fmaxf(v.w + m4.w, 0.f);
        o4[i] = v;
    }
}

// ---------------------------------------------------------------------------
extern "C" void kernel_launch(void* const* d_in, const int* in_sizes, int n_in,
                              void* d_out, int out_size) {
    const int*   x        = (const int*)d_in[0];
    const int*   ea       = (const int*)d_in[1];
    const float* bond_n   = (const float*)d_in[2];
    const float* atom_emb = (const float*)d_in[3];
    const float* bond_emb = (const float*)d_in[4];
    const float* Wi_w     = (const float*)d_in[5];
    const float* Wi_b     = (const float*)d_in[6];
    const float* Wm_w     = (const float*)d_in[7];
    const float* Wm_b     = (const float*)d_in[8];
    float* out = (float*)d_out;

    k_transpose<<<128, 256>>>(Wi_w);
    k_fused<<<G_TOT, 256>>>(x, ea, atom_emb, bond_emb, Wi_b, bond_n, out);
    k_tail<<<TB, 256>>>(Wm_w, Wm_b, out);
}